// round 11
// baseline (speedup 1.0000x reference)
#include <cuda_runtime.h>
#include <cuda_fp16.h>
#include <math.h>
#include <stdint.h>

#define NB 8
#define NC 256
#define NTOK 16384

__device__ __forceinline__ uint32_t s2u(const void* p) {
    uint32_t a;
    asm("{ .reg .u64 t; cvta.to.shared.u64 t, %1; cvt.u32.u64 %0, t; }" : "=r"(a) : "l"(p));
    return a;
}
__device__ __forceinline__ void ldm_x4(uint32_t r[4], uint32_t addr) {
    asm volatile("ldmatrix.sync.aligned.m8n8.x4.shared.b16 {%0,%1,%2,%3}, [%4];"
        : "=r"(r[0]), "=r"(r[1]), "=r"(r[2]), "=r"(r[3]) : "r"(addr));
}
__device__ __forceinline__ void mma_f16(float c[4], const uint32_t a[4], const uint32_t b[2]) {
    asm volatile("mma.sync.aligned.m16n8k16.row.col.f32.f16.f16.f32 "
        "{%0,%1,%2,%3}, {%4,%5,%6,%7}, {%8,%9}, {%0,%1,%2,%3};"
        : "+f"(c[0]), "+f"(c[1]), "+f"(c[2]), "+f"(c[3])
        : "r"(a[0]), "r"(a[1]), "r"(a[2]), "r"(a[3]), "r"(b[0]), "r"(b[1]));
}
__device__ __forceinline__ void cpa16(uint32_t s, const void* g) {
    asm volatile("cp.async.cg.shared.global [%0], [%1], 16;"
        :: "r"(s), "l"(__cvta_generic_to_global(g)));
}
#define CP_COMMIT() asm volatile("cp.async.commit_group;" ::: "memory")
#define CP_WAIT0() asm volatile("cp.async.wait_group 0;" ::: "memory")

// ---------------- device scratch ----------------
__device__ float g_T[128 * 128];
__device__ float g_WkT[NC * NC];
__device__ float g_RK[128 * NC];
__device__ float g_PK[128 * NC];
__device__ float g_spart[(size_t)NB * 256 * 8192];
__device__ float g_S[NB * 8192];
__device__ float g_M[NB * NC * NC];          // transposed [co][ci]
__device__ float g_biasq[NB * NC];
__device__ float g_RQ[NB * 128 * NC];
__device__ float g_PQ[NB * 128 * NC];
__device__ __align__(16) __half g_Bw[2][256][264];      // Wk, Wv fp16 [co][ci]
__device__ __align__(16) __half g_Bm[NB][256][264];     // M fp16 [co][ci]

// t1 smem (bytes): A@0 33792 | B@33792 33792 | KT@67584 9216 | VT@76800 9216
#define T1_B   33792
#define KT_OFF 67584
#define VT_OFF 76800
#define T1_TOT 86016
// t3 smem: A@0 33792 | B@33792 33792 | stg overlays 0..67584 | mu@67584 | rs@67904
#define T3_B   33792
#define T3_MU  67584
#define T3_RS  67904
#define T3_TOT 68224

// ---------------- preps ----------------
__global__ void prep0_kernel(const float* __restrict__ Wk, const float* __restrict__ Wv) {
    int idx = blockIdx.x * 256 + threadIdx.x;
    int co = idx >> 8, ci = idx & 255;
    g_WkT[ci * NC + co] = Wk[idx];
    g_Bw[0][co][ci] = __float2half_rn(Wk[idx]);
    g_Bw[1][co][ci] = __float2half_rn(Wv[idx]);
    if (idx < 128 * 128) {
        int p = idx >> 7, c = idx & 127, j = c >> 1;
        float dimt = powf(10000.0f, (float)j * (1.0f / 64.0f));
        float t = (float)(p + 1) * (6.283185307179586f / (128.0f + 1e-6f)) / dimt;
        g_T[idx] = (c & 1) ? cosf(t) : sinf(t);
    }
}

__global__ void prep1_kernel() {
    int table = blockIdx.x >> 3, chunk = blockIdx.x & 7;
    int n = chunk * 32 + (threadIdx.x & 31);
    int yg = threadIdx.x >> 5;
    float acc[16];
#pragma unroll
    for (int i = 0; i < 16; i++) acc[i] = 0.f;
    const float* W = g_WkT + (table ? 128 * NC : 0);
#pragma unroll 4
    for (int c = 0; c < 128; c++) {
        float w = W[c * NC + n];
#pragma unroll
        for (int yy = 0; yy < 16; yy++) acc[yy] += g_T[(yg * 16 + yy) * 128 + c] * w;
    }
    float* dst = table ? g_PK : g_RK;
#pragma unroll
    for (int yy = 0; yy < 16; yy++) dst[(yg * 16 + yy) * NC + n] = acc[yy];
}

// x[ci][tok] -> A[tok 64][ci 256 pad 264] fp16
__device__ __forceinline__ void load_x_tile(char* smem, const float* __restrict__ xb, int tid) {
    int tok = tid & 63, cig = tid >> 6;
#pragma unroll 1
    for (int p = 0; p < 8; p++) {
        int ci0 = (cig + p * 4) * 8;
        __half hv[8];
#pragma unroll
        for (int j = 0; j < 8; j++)
            hv[j] = __float2half_rn(xb[(size_t)(ci0 + j) * NTOK + tok]);
        *(uint4*)(smem + tok * 528 + ci0 * 2) = *(uint4*)hv;
    }
}

// ---------------- T1: fp16 K/V proj + register LN + fp16 scores (64-tok, 2 CTA/SM) ----------------
__global__ void __launch_bounds__(256, 2) t1_kernel(
    const float* __restrict__ x,
    const float* __restrict__ bk, const float* __restrict__ bv,
    const float* __restrict__ gK, const float* __restrict__ bKp,
    const float* __restrict__ gV, const float* __restrict__ bVp)
{
    extern __shared__ char smem[];
    const int tid = threadIdx.x, w = tid >> 5, lane = tid & 31;
    const int blk = blockIdx.x, b = blockIdx.y;
    const int n0 = blk * 64, y = n0 >> 7, x0 = n0 & 127;
    uint32_t sb = s2u(smem);

    const int mt = w >> 1, ch = w & 1;   // mt 0..3 (m16 tile), ch 0..1 (n32 chunk)
    const uint32_t aH0 = sb + (mt * 16 + (lane & 15)) * 528 + ((lane & 16) ? 16 : 0);
    const int blrow = (lane & 7) + ((lane & 16) ? 8 : 0);
    const int blcol2 = (lane & 8) ? 16 : 0;

    load_x_tile(smem, x + ((size_t)b * NC) * NTOK + n0, tid);

#pragma unroll 1
    for (int s = 0; s < 8; s++) {
        const int nc = s >> 1, op = s & 1;
        __syncthreads();    // prior B reads + KT/VT reuse done
        for (int i = tid; i < 2112; i += 256)
            cpa16(sb + T1_B + i * 16, ((const uint4*)&g_Bw[op][nc * 64][0]) + i);
        CP_COMMIT(); CP_WAIT0();
        __syncthreads();

        float acc[4][4];
#pragma unroll
        for (int f = 0; f < 4; f++)
#pragma unroll
            for (int j = 0; j < 4; j++) acc[f][j] = 0.f;

        const uint32_t bbase = sb + T1_B + (ch * 32 + blrow) * 528 + blcol2;
#pragma unroll 4
        for (int k = 0; k < 16; k++) {
            uint32_t ah[4];
            ldm_x4(ah, aH0 + k * 32);
#pragma unroll
            for (int q = 0; q < 2; q++) {
                uint32_t bb[4];
                ldm_x4(bb, bbase + q * 16 * 528 + k * 32);
                mma_f16(acc[q * 2], ah, bb);
                mma_f16(acc[q * 2 + 1], ah, bb + 2);
            }
        }

        // epilogue: +pos/bias -> register LN -> transposed fp16 store to KT/VT
        {
            const int r0 = lane >> 2, cq = (lane & 3) * 2;
            const int rowA = mt * 16 + r0, rowB = rowA + 8;
            const int head = nc * 2 + ch;
            float vA[8], vB[8];
            if (op == 0) {
#pragma unroll
                for (int f = 0; f < 4; f++) {
                    int co = nc * 64 + ch * 32 + f * 8 + cq;
                    float2 rk = *(const float2*)&g_RK[y * NC + co];
                    float2 bk2 = *(const float2*)&bk[co];
                    float2 pa = *(const float2*)&g_PK[(x0 + rowA) * NC + co];
                    float2 pb = *(const float2*)&g_PK[(x0 + rowB) * NC + co];
                    vA[f * 2] = acc[f][0] + rk.x + pa.x + bk2.x;
                    vA[f * 2 + 1] = acc[f][1] + rk.y + pa.y + bk2.y;
                    vB[f * 2] = acc[f][2] + rk.x + pb.x + bk2.x;
                    vB[f * 2 + 1] = acc[f][3] + rk.y + pb.y + bk2.y;
                }
            } else {
#pragma unroll
                for (int f = 0; f < 4; f++) {
                    int co = nc * 64 + ch * 32 + f * 8 + cq;
                    float2 bv2 = *(const float2*)&bv[co];
                    vA[f * 2] = acc[f][0] + bv2.x;
                    vA[f * 2 + 1] = acc[f][1] + bv2.y;
                    vB[f * 2] = acc[f][2] + bv2.x;
                    vB[f * 2 + 1] = acc[f][3] + bv2.y;
                }
            }
            float sA = 0.f, s2A = 0.f, sB = 0.f, s2B = 0.f;
#pragma unroll
            for (int j = 0; j < 8; j++) {
                sA += vA[j]; s2A += vA[j] * vA[j];
                sB += vB[j]; s2B += vB[j] * vB[j];
            }
#pragma unroll
            for (int off = 1; off < 4; off <<= 1) {
                sA += __shfl_xor_sync(0xffffffffu, sA, off);
                s2A += __shfl_xor_sync(0xffffffffu, s2A, off);
                sB += __shfl_xor_sync(0xffffffffu, sB, off);
                s2B += __shfl_xor_sync(0xffffffffu, s2B, off);
            }
            float muA = sA * (1.f / 32.f);
            float rsA = rsqrtf(s2A * (1.f / 32.f) - muA * muA + 1e-5f);
            float muB = sB * (1.f / 32.f);
            float rsB = rsqrtf(s2B * (1.f / 32.f) - muB * muB + 1e-5f);
            const float* gg = op ? gV : gK;
            const float* be = op ? bVp : bKp;
            uint32_t base = sb + (op ? VT_OFF : KT_OFF);
#pragma unroll
            for (int f = 0; f < 4; f++)
#pragma unroll
                for (int j = 0; j < 2; j++) {
                    int d = f * 8 + cq + j;
                    float g = gg[head * 32 + d], bb2 = be[head * 32 + d];
                    uint32_t rowoff = (uint32_t)(ch * 32 + d) * 144;
                    __half ha = __float2half_rn((vA[f * 2 + j] - muA) * rsA * g + bb2);
                    __half hb = __float2half_rn((vB[f * 2 + j] - muB) * rsB * g + bb2);
                    asm volatile("st.shared.u16 [%0], %1;" :: "r"(base + rowoff + rowA * 2), "h"(*(unsigned short*)&ha));
                    asm volatile("st.shared.u16 [%0], %1;" :: "r"(base + rowoff + rowB * 2), "h"(*(unsigned short*)&hb));
                }
        }

        if (op == 1) {
            __syncthreads();
            // scores: S_h[d][e] = sum_tok K[tok][d] V[tok][e], k = 64 tokens
            const int hl = w >> 2, dt = (w >> 1) & 1, et = w & 1;
            const uint32_t aB = sb + KT_OFF + (hl * 32 + dt * 16 + (lane & 15)) * 144
                              + ((lane & 16) ? 16 : 0);
            const uint32_t bB = sb + VT_OFF + (hl * 32 + et * 16 + blrow) * 144 + blcol2;
            float sc[2][4];
#pragma unroll
            for (int q = 0; q < 2; q++)
#pragma unroll
                for (int j = 0; j < 4; j++) sc[q][j] = 0.f;
#pragma unroll
            for (int k = 0; k < 4; k++) {
                uint32_t a[4], bb[4];
                ldm_x4(a, aB + k * 32);
                ldm_x4(bb, bB + k * 32);
                mma_f16(sc[0], a, bb);
                mma_f16(sc[1], a, bb + 2);
            }
            float* dst = g_spart + ((size_t)(b * 256 + blk)) * 8192 + (nc * 2 + hl) * 1024;
            int d0 = dt * 16 + (lane >> 2);
#pragma unroll
            for (int q = 0; q < 2; q++) {
                int e0 = et * 16 + q * 8 + (lane & 3) * 2;
                dst[d0 * 32 + e0] = sc[q][0];
                dst[d0 * 32 + e0 + 1] = sc[q][1];
                dst[(d0 + 8) * 32 + e0] = sc[q][2];
                dst[(d0 + 8) * 32 + e0 + 1] = sc[q][3];
            }
        }
    }
}

// ---------------- k2 chain ----------------
__global__ void k2_reduce() {
    int b = blockIdx.x >> 5, seg = blockIdx.x & 31;
    int base = seg * 256 + threadIdx.x;
    float s = 0.f;
#pragma unroll 8
    for (int rb = 0; rb < 256; rb++) s += g_spart[((size_t)(b * 256 + rb)) * 8192 + base];
    g_S[b * 8192 + base] = s * (1.0f / 16384.0f);
}

__global__ void k2b_buildM(const float* __restrict__ Wq, const float* __restrict__ bq) {
    __shared__ float Wqs[256 * 33];
    int chunk = blockIdx.x, b = blockIdx.y;
    int co = threadIdx.x, h = co >> 5, e = co & 31;
    for (int idx = threadIdx.x; idx < 8192; idx += 256) {
        int row = idx >> 5, cil = idx & 31;
        Wqs[row * 33 + cil] = Wq[row * NC + chunk * 32 + cil];
    }
    float Scol[32];
#pragma unroll
    for (int d = 0; d < 32; d++) Scol[d] = g_S[b * 8192 + h * 1024 + d * 32 + e];
    __syncthreads();
    for (int cil = 0; cil < 32; cil++) {
        float m = 0.f;
#pragma unroll
        for (int d = 0; d < 32; d++) m += Wqs[(h * 32 + d) * 33 + cil] * Scol[d];
        g_M[(size_t)b * 65536 + (size_t)co * NC + chunk * 32 + cil] = m;
        g_Bm[b][co][chunk * 32 + cil] = __float2half_rn(m);
    }
    if (chunk == 0) {
        float bb = 0.f;
#pragma unroll
        for (int d = 0; d < 32; d++) bb += bq[h * 32 + d] * Scol[d];
        g_biasq[b * NC + co] = bb;
    }
}

__global__ void k2c_rqpq() {
    __shared__ float Ts[128];
    int p = blockIdx.x, b = blockIdx.y;
    int co = threadIdx.x;
    if (co < 128) Ts[co] = g_T[p * 128 + co];
    __syncthreads();
    const float4* Mr = (const float4*)(g_M + (size_t)b * 65536 + (size_t)co * NC);
    float accR = 0.f, accP = 0.f;
#pragma unroll 8
    for (int c4 = 0; c4 < 32; c4++) {
        float4 m0 = Mr[c4], m1 = Mr[32 + c4];
        float4 t4 = *(const float4*)&Ts[c4 * 4];
        accR += t4.x * m0.x + t4.y * m0.y + t4.z * m0.z + t4.w * m0.w;
        accP += t4.x * m1.x + t4.y * m1.y + t4.z * m1.z + t4.w * m1.w;
    }
    g_RQ[(b * 128 + p) * NC + co] = accR;
    g_PQ[(b * 128 + p) * NC + co] = accP;
}

// ---------------- T3: fp16 out GEMM + x2 + LN + transposed store (64-tok) ----------------
__global__ void __launch_bounds__(256, 2) t3_kernel(
    const float* __restrict__ x,
    const float* __restrict__ g_ln, const float* __restrict__ b_ln,
    float* __restrict__ out)
{
    extern __shared__ char smem[];
    const int tid = threadIdx.x, w = tid >> 5, lane = tid & 31;
    const int blk = blockIdx.x, b = blockIdx.y;
    const int n0 = blk * 64, y = n0 >> 7, x0 = n0 & 127;
    uint32_t sb = s2u(smem);

    const int mt = w >> 1, ch = w & 1;
    const uint32_t aH0 = sb + (mt * 16 + (lane & 15)) * 528 + ((lane & 16) ? 16 : 0);
    const int blrow = (lane & 7) + ((lane & 16) ? 8 : 0);
    const int blcol2 = (lane & 8) ? 16 : 0;

    load_x_tile(smem, x + ((size_t)b * NC) * NTOK + n0, tid);

    float acc[4][4][4];
#pragma unroll 1
    for (int s = 0; s < 4; s++) {
        __syncthreads();
        for (int i = tid; i < 2112; i += 256)
            cpa16(sb + T3_B + i * 16, ((const uint4*)&g_Bm[b][s * 64][0]) + i);
        CP_COMMIT(); CP_WAIT0();
        __syncthreads();

#pragma unroll
        for (int f = 0; f < 4; f++)
#pragma unroll
            for (int j = 0; j < 4; j++) acc[s][f][j] = 0.f;

        const uint32_t bbase = sb + T3_B + (ch * 32 + blrow) * 528 + blcol2;
#pragma unroll 4
        for (int k = 0; k < 16; k++) {
            uint32_t ah[4];
            ldm_x4(ah, aH0 + k * 32);
#pragma unroll
            for (int q = 0; q < 2; q++) {
                uint32_t bb[4];
                ldm_x4(bb, bbase + q * 16 * 528 + k * 32);
                mma_f16(acc[s][q * 2], ah, bb);
                mma_f16(acc[s][q * 2 + 1], ah, bb + 2);
            }
        }
    }
    __syncthreads();

    float* stg = (float*)smem;          // [64][264]
    float* mus = (float*)(smem + T3_MU);
    float* rss = (float*)(smem + T3_RS);
    {
        int r0 = lane >> 2, cq = (lane & 3) * 2;
        int rowA = mt * 16 + r0, rowB = rowA + 8;
#pragma unroll
        for (int s = 0; s < 4; s++)
#pragma unroll
            for (int f = 0; f < 4; f++) {
                int co = s * 64 + ch * 32 + f * 8 + cq;
                float2 rq = *(const float2*)&g_RQ[(b * 128 + y) * NC + co];
                float2 qb = *(const float2*)&g_biasq[b * NC + co];
                float2 pa = *(const float2*)&g_PQ[(b * 128 + x0 + rowA) * NC + co];
                float2 pb = *(const float2*)&g_PQ[(b * 128 + x0 + rowB) * NC + co];
                stg[rowA * 264 + co] = 2.f * (acc[s][f][0] + rq.x + qb.x + pa.x);
                stg[rowA * 264 + co + 1] = 2.f * (acc[s][f][1] + rq.y + qb.y + pa.y);
                stg[rowB * 264 + co] = 2.f * (acc[s][f][2] + rq.x + qb.x + pb.x);
                stg[rowB * 264 + co + 1] = 2.f * (acc[s][f][3] + rq.y + qb.y + pb.y);
            }
    }
    __syncthreads();

    {
        int token = tid >> 2, q = tid & 3;
        float s = 0.f, s2 = 0.f;
#pragma unroll
        for (int jj = 0; jj < 16; jj++) {
            float4 v = *(const float4*)&stg[token * 264 + q * 64 + jj * 4];
            s += v.x + v.y + v.z + v.w;
            s2 += v.x * v.x + v.y * v.y + v.z * v.z + v.w * v.w;
        }
#pragma unroll
        for (int off = 1; off < 4; off <<= 1) {
            s += __shfl_xor_sync(0xffffffffu, s, off);
            s2 += __shfl_xor_sync(0xffffffffu, s2, off);
        }
        if (q == 0) {
            float mu = s * (1.f / 256.f);
            mus[token] = mu;
            rss[token] = rsqrtf(s2 * (1.f / 256.f) - mu * mu + 1e-5f);
        }
    }
    __syncthreads();

    {
        int t = tid & 63, cg = tid >> 6;
        float mu = mus[t], rs = rss[t];
        size_t obase = ((size_t)b * NC) * NTOK + n0 + t;
#pragma unroll 4
        for (int p = 0; p < 64; p++) {
            int co = cg * 64 + p;
            out[obase + (size_t)co * NTOK] = (stg[t * 264 + co] - mu) * rs * g_ln[co] + b_ln[co];
        }
    }
}

// ---------------- launch ----------------
extern "C" void kernel_launch(void* const* d_in, const int* in_sizes, int n_in,
                              void* d_out, int out_size) {
    const float* x    = (const float*)d_in[0];
    const float* Wq   = (const float*)d_in[1];
    const float* bq   = (const float*)d_in[2];
    const float* Wk   = (const float*)d_in[3];
    const float* bk   = (const float*)d_in[4];
    const float* Wv   = (const float*)d_in[5];
    const float* bv   = (const float*)d_in[6];
    const float* gK   = (const float*)d_in[7];
    const float* bK   = (const float*)d_in[8];
    const float* gV   = (const float*)d_in[9];
    const float* bV   = (const float*)d_in[10];
    const float* g_ln = (const float*)d_in[11];
    const float* b_ln = (const float*)d_in[12];
    float* out = (float*)d_out;

    cudaFuncSetAttribute(t1_kernel, cudaFuncAttributeMaxDynamicSharedMemorySize, T1_TOT);
    cudaFuncSetAttribute(t3_kernel, cudaFuncAttributeMaxDynamicSharedMemorySize, T3_TOT);

    prep0_kernel<<<256, 256>>>(Wk, Wv);
    prep1_kernel<<<16, 256>>>();
    t1_kernel<<<dim3(256, 8), 256, T1_TOT>>>(x, bk, bv, gK, bK, gV, bV);
    k2_reduce<<<256, 256>>>();
    k2b_buildM<<<dim3(8, 8), 256>>>(Wq, bq);
    k2c_rqpq<<<dim3(128, 8), 256>>>();
    t3_kernel<<<dim3(256, 8), 256, T3_TOT>>>(x, g_ln, b_ln, out);
}